// round 15
// baseline (speedup 1.0000x reference)
#include <cuda_runtime.h>
#include <cstdint>

// 2D acoustic FDTD, 500 steps, 8 shots, 256x256, 128 recs/shot.
// TWO SHOTS PER 8-CTA CLUSTER (grid 32): shot A and shot B interleave so each
// shot's mbarrier cluster-barrier latency hides behind the other shot's
// compute. Packed f32x2 stencil; cur-in-registers; prev read from the nxt
// buffer (old contents) -> only 8 loop-carried regs per shot.

#define DT 0.001f
#define DX 10.0f

constexpr int NT   = 500;
constexpr int NS   = 8;
constexpr int NZ   = 256;
constexpr int NXC  = 256;
constexpr int NREC = 128;

constexpr int CSZ  = 8;
constexpr int ROWS = NZ / CSZ;          // 32
constexpr int NTHREADS = 1024;
constexpr int COL4 = NXC / 4;           // 64
constexpr int RG   = NTHREADS / COL4;   // 16
constexpr int RPT  = ROWS / RG;         // 2

constexpr int BUF_ELEMS = ROWS * NXC;        // 8192 floats
constexpr uint32_t BUF_BYTES = BUF_ELEMS * 4;  // 32768
constexpr int OFF_AMPA = 4 * BUF_ELEMS;
constexpr int OFF_AMPB = OFF_AMPA + NT;
constexpr size_t SMEM_BYTES = (size_t)(OFF_AMPB + NT + 32) * sizeof(float);

typedef unsigned long long u64;

// ---------------------------------------------------------------- PTX helpers
__device__ __forceinline__ uint32_t cvta_smem(const void* p) {
    return (uint32_t)__cvta_generic_to_shared(p);
}
__device__ __forceinline__ uint32_t mapa_cluster(uint32_t laddr, uint32_t rank) {
    uint32_t r;
    asm("mapa.shared::cluster.u32 %0, %1, %2;" : "=r"(r) : "r"(laddr), "r"(rank));
    return r;
}
__device__ __forceinline__ ulonglong2 ld_dsmem_u64x2(uint32_t addr) {
    ulonglong2 v;
    asm volatile("ld.shared::cluster.v2.u64 {%0,%1}, [%2];"
                 : "=l"(v.x), "=l"(v.y) : "r"(addr));
    return v;
}
__device__ __forceinline__ void cluster_sync_() {
    asm volatile("barrier.cluster.arrive.aligned;" ::: "memory");
    asm volatile("barrier.cluster.wait.aligned;" ::: "memory");
}
__device__ __forceinline__ uint32_t cluster_rank_() {
    uint32_t r;
    asm("mov.u32 %0, %%cluster_ctarank;" : "=r"(r));
    return r;
}
__device__ __forceinline__ void mbar_init(uint32_t addr, uint32_t count) {
    asm volatile("mbarrier.init.shared.b64 [%0], %1;" :: "r"(addr), "r"(count) : "memory");
}
__device__ __forceinline__ void mbar_arrive_remote(uint32_t addr) {
    asm volatile("mbarrier.arrive.release.cluster.shared::cluster.b64 _, [%0];"
                 :: "r"(addr) : "memory");
}
__device__ __forceinline__ void mbar_wait(uint32_t addr, uint32_t parity) {
    asm volatile(
        "{\n\t"
        ".reg .pred P;\n\t"
        "WL%=:\n\t"
        "mbarrier.try_wait.parity.acquire.cluster.shared::cta.b64 P, [%0], %1, 0x989680;\n\t"
        "@!P bra WL%=;\n\t"
        "}"
        :: "r"(addr), "r"(parity) : "memory");
}

// ---- packed f32x2 ops -------------------------------------------------------
__device__ __forceinline__ u64 pk(float a, float b) {
    u64 r; asm("mov.b64 %0, {%1, %2};" : "=l"(r) : "f"(a), "f"(b)); return r;
}
__device__ __forceinline__ float2 upk(u64 v) {
    float2 f; asm("mov.b64 {%0, %1}, %2;" : "=f"(f.x), "=f"(f.y) : "l"(v)); return f;
}
__device__ __forceinline__ u64 addx2(u64 a, u64 b) {
    u64 r; asm("add.rn.f32x2 %0, %1, %2;" : "=l"(r) : "l"(a), "l"(b)); return r;
}
__device__ __forceinline__ u64 mulx2(u64 a, u64 b) {
    u64 r; asm("mul.rn.f32x2 %0, %1, %2;" : "=l"(r) : "l"(a), "l"(b)); return r;
}
__device__ __forceinline__ u64 fmax2(u64 a, u64 b, u64 c) {
    u64 r; asm("fma.rn.f32x2 %0, %1, %2, %3;" : "=l"(r) : "l"(a), "l"(b), "l"(c)); return r;
}

// ---------------------------------------------------------------- kernel
__global__ void __cluster_dims__(CSZ, 1, 1) __launch_bounds__(NTHREADS, 1)
wave_kernel(const float* __restrict__ x,     // (NT, NS)
            const float* __restrict__ vp,    // (NZ, NXC)
            const int*   __restrict__ src,   // (NS, 2)
            const int*   __restrict__ rec,   // (NS, NREC, 2)
            float*       __restrict__ out)   // (NT, NS, NREC)
{
    extern __shared__ float sm[];
    float* bufA0 = sm;
    float* bufA1 = sm + BUF_ELEMS;
    float* bufB0 = sm + 2 * BUF_ELEMS;
    float* bufB1 = sm + 3 * BUF_ELEMS;
    float* ampA  = sm + OFF_AMPA;
    float* ampB  = sm + OFF_AMPB;

    __shared__ uint64_t barA, barB;       // per-shot full cluster barriers
    __shared__ int rcntA, rcntB;
    __shared__ int2 rlistA[NREC], rlistB[NREC];

    const int tid  = threadIdx.x;
    const uint32_t rank = cluster_rank_();
    const int cl   = blockIdx.x / CSZ;    // cluster id 0..3
    const int shotA = 2 * cl;
    const int shotB = 2 * cl + 1;

    const int col4 = tid & (COL4 - 1);
    const int rg   = tid >> 6;            // 0..15
    const int lr0  = rg * RPT;
    const int xcol = col4 * 4;
    const bool has_n = (rank > 0);
    const bool has_s = (rank < CSZ - 1);
    const bool bndN = (rg == 0 && has_n);
    const bool bndS = (rg == RG - 1 && has_s);

    // --- init ----------------------------------------------------------------
    for (int i = tid; i < 4 * BUF_ELEMS; i += NTHREADS) sm[i] = 0.f;
    for (int i = tid; i < NT; i += NTHREADS) {
        const int toff = (i + 2 < NT - 1) ? i + 2 : NT - 1;
        ampA[i] = x[i * NS + shotA] + x[toff * NS + shotA];
        ampB[i] = x[i * NS + shotB] + x[toff * NS + shotB];
    }
    if (tid == 0) {
        rcntA = 0; rcntB = 0;
        mbar_init(cvta_smem(&barA), CSZ);
        mbar_init(cvta_smem(&barB), CSZ);
    }
    __syncthreads();

    // claim receivers owned by this CTA, per shot
    if (tid < NREC) {
        const int gi = shotA * NREC + tid;
        const int rz = rec[gi * 2 + 0];
        const int rx = rec[gi * 2 + 1];
        if ((uint32_t)(rz >> 5) == rank) {
            int s = atomicAdd(&rcntA, 1);
            rlistA[s] = make_int2((rz & 31) * NXC + rx, shotA * NREC + tid);
        }
    } else if (tid < 2 * NREC) {
        const int k = tid - NREC;
        const int gi = shotB * NREC + k;
        const int rz = rec[gi * 2 + 0];
        const int rx = rec[gi * 2 + 1];
        if ((uint32_t)(rz >> 5) == rank) {
            int s = atomicAdd(&rcntB, 1);
            rlistB[s] = make_int2((rz & 31) * NXC + rx, shotB * NREC + k);
        }
    }

    // c2 in packed registers (shared between shots: same vp)
    u64 k01[RPT], k23[RPT];
    const float sc = DT / DX;
#pragma unroll
    for (int j = 0; j < RPT; j++) {
        const int g = (int)rank * ROWS + lr0 + j;
        float4 v = *(const float4*)(vp + g * NXC + xcol);
        float a = v.x * sc, b = v.y * sc, c = v.z * sc, d = v.w * sc;
        k01[j] = pk(a * a, b * b);
        k23[j] = pk(c * c, d * d);
    }

    const u64 TWO2 = pk(2.f, 2.f);
    const u64 NEG4 = pk(-4.f, -4.f);
    const u64 NEG1 = pk(-1.f, -1.f);

    // loop-carried field registers: cur pairs per shot (zero at t=0)
    u64 cA01[RPT], cA23[RPT], cB01[RPT], cB23[RPT];
#pragma unroll
    for (int j = 0; j < RPT; j++) { cA01[j] = 0; cA23[j] = 0; cB01[j] = 0; cB23[j] = 0; }

    // source ownership per shot
    const int szA = src[shotA * 2 + 0], sxA = src[shotA * 2 + 1];
    const int szB = src[shotB * 2 + 0], sxB = src[shotB * 2 + 1];
    const int sjA = szA - ((int)rank * ROWS + lr0);
    const int sjB = szB - ((int)rank * ROWS + lr0);
    const bool shA = (sjA >= 0 && sjA < RPT && sxA >= xcol && sxA < xcol + 4);
    const bool shB = (sjB >= 0 && sjB < RPT && sxB >= xcol && sxB < xcol + 4);
    const int scA = sxA - xcol;
    const int scB = sxB - xcol;

    // DSMEM halo base addresses (shot A, parity 0); derive others via +imm
    const uint32_t saA0 = cvta_smem(bufA0);
    uint32_t nh_base = 0, sh_base = 0;
    if (bndN) {
        const uint32_t off = (uint32_t)((ROWS - 1) * NXC + xcol) * 4u;
        nh_base = mapa_cluster(saA0 + off, rank - 1);
    }
    if (bndS) {
        const uint32_t off = (uint32_t)(xcol) * 4u;
        sh_base = mapa_cluster(saA0 + off, rank + 1);
    }

    // remote arrive targets: tid<8 -> CTA tid's barA; tid 8..15 -> barB
    uint32_t arr = 0;
    const bool doArrA = (tid < CSZ);
    const bool doArrB = (tid >= CSZ && tid < 2 * CSZ);
    if (doArrA) arr = mapa_cluster(cvta_smem(&barA), (uint32_t)tid);
    if (doArrB) arr = mapa_cluster(cvta_smem(&barB), (uint32_t)(tid - CSZ));
    const uint32_t baA = cvta_smem(&barA);
    const uint32_t baB = cvta_smem(&barB);

    __syncthreads();
    const bool sampA = (tid < rcntA);
    const bool sampB = (tid < rcntB);
    int roffA = 0, roffB = 0;
    float* outpA = out;
    float* outpB = out;
    if (sampA) { int2 e = rlistA[tid]; roffA = e.x; outpA = out + e.y; }
    if (sampB) { int2 e = rlistB[tid]; roffB = e.x; outpB = out + e.y; }

    cluster_sync_();  // zeroed buffers + initialized barriers visible

    // --- one shot-step (prev read from nxt's old contents) -------------------
    auto shot_step = [&](u64 (&c01)[RPT], u64 (&c23)[RPT],
                         const float* __restrict__ cur, float* __restrict__ nxt,
                         uint32_t nh, uint32_t sh,
                         const float* amp_tab, bool sh_here, int ssj, int sscomp,
                         int t) {
        u64 n01, n23;
        if (rg == 0) {
            if (has_n) { ulonglong2 v = ld_dsmem_u64x2(nh); n01 = v.x; n23 = v.y; }
            else       { n01 = 0; n23 = 0; }
        } else {
            ulonglong2 v = *(const ulonglong2*)(cur + (lr0 - 1) * NXC + xcol);
            n01 = v.x; n23 = v.y;
        }

#pragma unroll
        for (int j = 0; j < RPT; j++) {
            const int lr = lr0 + j;
            const u64 cv01 = c01[j], cv23 = c23[j];

            // prev = old contents of nxt (p(t-1)); own rows only -> in-place safe
            const ulonglong2 pv = *(const ulonglong2*)(nxt + lr * NXC + xcol);

            u64 s01, s23;
            if (j < RPT - 1) {
                s01 = c01[j + 1]; s23 = c23[j + 1];
            } else if (rg == RG - 1) {
                if (has_s) { ulonglong2 v = ld_dsmem_u64x2(sh); s01 = v.x; s23 = v.y; }
                else       { s01 = 0; s23 = 0; }
            } else {
                ulonglong2 v = *(const ulonglong2*)(cur + (lr + 1) * NXC + xcol);
                s01 = v.x; s23 = v.y;
            }

            const float lft = (xcol > 0)       ? cur[lr * NXC + xcol - 1] : 0.f;
            const float rgt = (xcol + 4 < NXC) ? cur[lr * NXC + xcol + 4] : 0.f;

            const float2 clo = upk(cv01), chi = upk(cv23);
            const u64 L0 = pk(lft,   clo.x);
            const u64 M  = pk(clo.y, chi.x);
            const u64 R1 = pk(chi.y, rgt);

            u64 lap01 = addx2(addx2(n01, s01), addx2(L0, M));
            u64 lap23 = addx2(addx2(n23, s23), addx2(M, R1));
            lap01 = fmax2(cv01, NEG4, lap01);
            lap23 = fmax2(cv23, NEG4, lap23);

            u64 nv01 = fmax2(k01[j], lap01, fmax2(cv01, TWO2, mulx2(pv.x, NEG1)));
            u64 nv23 = fmax2(k23[j], lap23, fmax2(cv23, TWO2, mulx2(pv.y, NEG1)));

            if (sh_here && j == ssj) {
                const float amp = amp_tab[t];
                float2 lo = upk(nv01), hi = upk(nv23);
                if      (sscomp == 0) lo.x += amp;
                else if (sscomp == 1) lo.y += amp;
                else if (sscomp == 2) hi.x += amp;
                else                  hi.y += amp;
                nv01 = pk(lo.x, lo.y);
                nv23 = pk(hi.x, hi.y);
            }

            ulonglong2 st; st.x = nv01; st.y = nv23;
            *(ulonglong2*)(nxt + lr * NXC + xcol) = st;

            c01[j] = nv01; c23[j] = nv23;
            n01 = cv01; n23 = cv23;
        }
    };

    // --- main time loop, unrolled x2 for compile-time buffer parity ----------
    for (int t2 = 0; t2 < NT; t2 += 2) {
        // ===== step t2 (parity 0: cur=*0 bufs, nxt=*1 bufs) =====
        // shot A
        if (t2 > 0) {
            if (bndN) mbar_wait(baA, 1u);   // parity of (t2-1), odd
            if (bndS) mbar_wait(baA, 1u);
        }
        shot_step(cA01, cA23, bufA0, bufA1, nh_base, sh_base,
                  ampA, shA, sjA, scA, t2);
        __syncthreads();
        if (doArrA) mbar_arrive_remote(arr);
        if (sampA) { *outpA = bufA1[roffA]; outpA += NS * NREC; }

        // shot B (barB matured during A compute)
        if (t2 > 0) {
            if (bndN) mbar_wait(baB, 1u);
            if (bndS) mbar_wait(baB, 1u);
        }
        shot_step(cB01, cB23, bufB0, bufB1,
                  nh_base + 2u * BUF_BYTES, sh_base + 2u * BUF_BYTES,
                  ampB, shB, sjB, scB, t2);
        __syncthreads();
        if (doArrB) mbar_arrive_remote(arr);
        if (sampB) { *outpB = bufB1[roffB]; outpB += NS * NREC; }

        // ===== step t2+1 (parity 1: cur=*1 bufs, nxt=*0 bufs) =====
        // shot A
        if (bndN) mbar_wait(baA, 0u);       // parity of (t2), even
        if (bndS) mbar_wait(baA, 0u);
        shot_step(cA01, cA23, bufA1, bufA0,
                  nh_base + BUF_BYTES, sh_base + BUF_BYTES,
                  ampA, shA, sjA, scA, t2 + 1);
        __syncthreads();
        if (doArrA) mbar_arrive_remote(arr);
        if (sampA) { *outpA = bufA0[roffA]; outpA += NS * NREC; }

        // shot B
        if (bndN) mbar_wait(baB, 0u);
        if (bndS) mbar_wait(baB, 0u);
        shot_step(cB01, cB23, bufB1, bufB0,
                  nh_base + 3u * BUF_BYTES, sh_base + 3u * BUF_BYTES,
                  ampB, shB, sjB, scB, t2 + 1);
        __syncthreads();
        if (doArrB) mbar_arrive_remote(arr);
        if (sampB) { *outpB = bufB0[roffB]; outpB += NS * NREC; }
    }

    cluster_sync_();  // keep cluster smem alive until all CTAs fully done
}

// ---------------------------------------------------------------- launch
extern "C" void kernel_launch(void* const* d_in, const int* in_sizes, int n_in,
                              void* d_out, int out_size)
{
    const float* x   = (const float*)d_in[0];
    const float* vp  = (const float*)d_in[1];
    const int*   src = (const int*)d_in[2];
    const int*   rec = (const int*)d_in[3];
    float*       out = (float*)d_out;

    cudaFuncSetAttribute((const void*)wave_kernel,
                         cudaFuncAttributeMaxDynamicSharedMemorySize,
                         (int)SMEM_BYTES);

    wave_kernel<<<(NS / 2) * CSZ, NTHREADS, SMEM_BYTES>>>(x, vp, src, rec, out);
}

// round 16
// speedup vs baseline: 1.3578x; 1.3578x over previous
#include <cuda_runtime.h>
#include <cstdint>

// 2D acoustic FDTD, 500 steps, 8 shots, 256x256, 128 recs/shot.
// One persistent kernel; shot = 8-CTA cluster; field in SMEM + registers.
// TEMPORAL BLOCKING v2: 2 steps per cluster.sync via ghost-row recompute.
//  - ghost DSMEM inputs PREFETCHED before substep 1 (latency hidden)
//  - prev re-read from buffer (no np registers; 4-buffer rotation keeps it stable)
//  - packed f32x2 stencil (R14 math, identical IEEE op sequence)

#define DT 0.001f
#define DX 10.0f

constexpr int NT   = 500;
constexpr int NS   = 8;
constexpr int NZ   = 256;
constexpr int NXC  = 256;
constexpr int NREC = 128;

constexpr int CSZ  = 8;
constexpr int ROWS = NZ / CSZ;          // 32
constexpr int NTHREADS = 1024;
constexpr int COL4 = NXC / 4;           // 64
constexpr int RG   = NTHREADS / COL4;   // 16
constexpr int RPT  = ROWS / RG;         // 2

constexpr int BUF_ELEMS = ROWS * NXC;          // 8192 floats
constexpr uint32_t BB   = BUF_ELEMS * 4;       // 32768 bytes per buffer
constexpr int OFF_AMP   = 4 * BUF_ELEMS;
constexpr size_t SMEM_BYTES = (size_t)(OFF_AMP + NT + 32) * sizeof(float);

typedef unsigned long long u64;

// ---------------------------------------------------------------- PTX helpers
__device__ __forceinline__ uint32_t cvta_smem(const void* p) {
    return (uint32_t)__cvta_generic_to_shared(p);
}
__device__ __forceinline__ uint32_t mapa_cluster(uint32_t laddr, uint32_t rank) {
    uint32_t r;
    asm("mapa.shared::cluster.u32 %0, %1, %2;" : "=r"(r) : "r"(laddr), "r"(rank));
    return r;
}
__device__ __forceinline__ ulonglong2 ld_dsmem_u64x2(uint32_t addr) {
    ulonglong2 v;
    asm volatile("ld.shared::cluster.v2.u64 {%0,%1}, [%2];"
                 : "=l"(v.x), "=l"(v.y) : "r"(addr));
    return v;
}
__device__ __forceinline__ float ld_dsmem_f32(uint32_t addr) {
    float v;
    asm volatile("ld.shared::cluster.f32 %0, [%1];" : "=f"(v) : "r"(addr));
    return v;
}
__device__ __forceinline__ void cluster_sync_() {
    asm volatile("barrier.cluster.arrive.aligned;" ::: "memory");
    asm volatile("barrier.cluster.wait.aligned;" ::: "memory");
}
__device__ __forceinline__ uint32_t cluster_rank_() {
    uint32_t r;
    asm("mov.u32 %0, %%cluster_ctarank;" : "=r"(r));
    return r;
}

// ---- packed f32x2 ops -------------------------------------------------------
__device__ __forceinline__ u64 pk(float a, float b) {
    u64 r; asm("mov.b64 %0, {%1, %2};" : "=l"(r) : "f"(a), "f"(b)); return r;
}
__device__ __forceinline__ float2 upk(u64 v) {
    float2 f; asm("mov.b64 {%0, %1}, %2;" : "=f"(f.x), "=f"(f.y) : "l"(v)); return f;
}
__device__ __forceinline__ u64 addx2(u64 a, u64 b) {
    u64 r; asm("add.rn.f32x2 %0, %1, %2;" : "=l"(r) : "l"(a), "l"(b)); return r;
}
__device__ __forceinline__ u64 mulx2(u64 a, u64 b) {
    u64 r; asm("mul.rn.f32x2 %0, %1, %2;" : "=l"(r) : "l"(a), "l"(b)); return r;
}
__device__ __forceinline__ u64 fmax2(u64 a, u64 b, u64 c) {
    u64 r; asm("fma.rn.f32x2 %0, %1, %2, %3;" : "=l"(r) : "l"(a), "l"(b), "l"(c)); return r;
}

struct U2 { u64 a, b; };

// one FDTD point-update for 4 columns (two packed pairs). prev passed raw.
__device__ __forceinline__ U2 fdtd_pair(u64 cv01, u64 cv23, u64 n01, u64 n23,
                                        u64 s01, u64 s23, float lft, float rgt,
                                        u64 pv01, u64 pv23, u64 kk01, u64 kk23) {
    const u64 TWO2 = pk(2.f, 2.f);
    const u64 NEG4 = pk(-4.f, -4.f);
    const u64 NEG1 = pk(-1.f, -1.f);
    const float2 clo = upk(cv01), chi = upk(cv23);
    const u64 L0 = pk(lft,   clo.x);
    const u64 M  = pk(clo.y, chi.x);
    const u64 R1 = pk(chi.y, rgt);
    u64 lap01 = addx2(addx2(n01, s01), addx2(L0, M));
    u64 lap23 = addx2(addx2(n23, s23), addx2(M, R1));
    lap01 = fmax2(cv01, NEG4, lap01);
    lap23 = fmax2(cv23, NEG4, lap23);
    U2 r;
    r.a = fmax2(kk01, lap01, fmax2(cv01, TWO2, mulx2(pv01, NEG1)));
    r.b = fmax2(kk23, lap23, fmax2(cv23, TWO2, mulx2(pv23, NEG1)));
    return r;
}

// ---------------------------------------------------------------- kernel
__global__ void __cluster_dims__(CSZ, 1, 1) __launch_bounds__(NTHREADS, 1)
wave_kernel(const float* __restrict__ x,     // (NT, NS)
            const float* __restrict__ vp,    // (NZ, NXC)
            const int*   __restrict__ src,   // (NS, 2)
            const int*   __restrict__ rec,   // (NS, NREC, 2)
            float*       __restrict__ out)   // (NT, NS, NREC)
{
    extern __shared__ float sm[];
    float* P0 = sm;
    float* P1 = sm + BUF_ELEMS;
    float* P2 = sm + 2 * BUF_ELEMS;
    float* P3 = sm + 3 * BUF_ELEMS;
    float* amp_s = sm + OFF_AMP;

    __shared__ int rcnt;
    __shared__ int2 rlist[NREC];

    const int tid  = threadIdx.x;
    const uint32_t rank = cluster_rank_();
    const int shot = blockIdx.x / CSZ;

    const int col4 = tid & (COL4 - 1);
    const int rg   = tid >> 6;           // 0..15
    const int lr0  = rg * RPT;
    const int xcol = col4 * 4;
    const bool has_n = (rank > 0);
    const bool has_s = (rank < CSZ - 1);
    const bool bndN = (rg == 0 && has_n);
    const bool bndS = (rg == RG - 1 && has_s);

    // --- init ----------------------------------------------------------------
    for (int i = tid; i < 4 * BUF_ELEMS; i += NTHREADS) sm[i] = 0.f;
    for (int i = tid; i < NT; i += NTHREADS) {
        const int toff = (i + 2 < NT - 1) ? i + 2 : NT - 1;
        amp_s[i] = x[i * NS + shot] + x[toff * NS + shot];
    }
    if (tid == 0) rcnt = 0;
    __syncthreads();

    // claim receivers owned by this CTA
    if (tid < NREC) {
        const int gi = shot * NREC + tid;
        const int rz = rec[gi * 2 + 0];
        const int rx = rec[gi * 2 + 1];
        if ((uint32_t)(rz >> 5) == rank) {
            int s = atomicAdd(&rcnt, 1);
            rlist[s] = make_int2((rz & 31) * NXC + rx, shot * NREC + tid);
        }
    }

    // c2 in packed registers (own rows + ghost row for boundary warps)
    u64 k01[RPT], k23[RPT], kg01 = 0, kg23 = 0;
    const float sc = DT / DX;
#pragma unroll
    for (int j = 0; j < RPT; j++) {
        const int g = (int)rank * ROWS + lr0 + j;
        float4 v = *(const float4*)(vp + g * NXC + xcol);
        float a = v.x * sc, b = v.y * sc, c = v.z * sc, d = v.w * sc;
        k01[j] = pk(a * a, b * b);
        k23[j] = pk(c * c, d * d);
    }
    if (bndN || bndS) {
        const int gz = bndN ? (int)rank * ROWS - 1 : (int)rank * ROWS + ROWS;
        float4 v = *(const float4*)(vp + gz * NXC + xcol);
        float a = v.x * sc, b = v.y * sc, c = v.z * sc, d = v.w * sc;
        kg01 = pk(a * a, b * b);
        kg23 = pk(c * c, d * d);
    }

    // loop-carried: cur pairs only (prev re-read from buffers)
    u64 c01[RPT], c23[RPT];
#pragma unroll
    for (int j = 0; j < RPT; j++) { c01[j] = 0; c23[j] = 0; }

    // source ownership (own rows + ghost row)
    const int sz = src[shot * 2 + 0];
    const int sx = src[shot * 2 + 1];
    const int sj = sz - ((int)rank * ROWS + lr0);
    const bool sin_x = (sx >= xcol && sx < xcol + 4);
    const bool shere = (sj >= 0 && sj < RPT && sin_x);
    const bool sghn = bndN && (sz == (int)rank * ROWS - 1) && sin_x;
    const bool sghs = bndS && (sz == (int)rank * ROWS + ROWS) && sin_x;
    const int scomp = sx - xcol;

    // neighbor DSMEM base addresses (buffer-0 base; add k*BB for buffer k)
    uint32_t nb30 = 0, nb31 = 0, sb0 = 0, sb1 = 0;
    {
        const uint32_t sa = cvta_smem(sm);
        if (bndN) {
            nb30 = mapa_cluster(sa + (uint32_t)((ROWS - 2) * NXC + xcol) * 4u, rank - 1);
            nb31 = mapa_cluster(sa + (uint32_t)((ROWS - 1) * NXC + xcol) * 4u, rank - 1);
        }
        if (bndS) {
            sb0 = mapa_cluster(sa + (uint32_t)(xcol) * 4u, rank + 1);
            sb1 = mapa_cluster(sa + (uint32_t)(NXC + xcol) * 4u, rank + 1);
        }
    }

    __syncthreads();
    const bool samp = (tid < rcnt);
    int roff = 0;
    float* outp = out;
    if (samp) {
        int2 e = rlist[tid];
        roff = e.x;
        outp = out + e.y;
    }

    cluster_sync_();  // zeroed buffers visible cluster-wide

    // --- one substep: cur/prev/nxt buffers; bn/bs = boundary N/S pairs -------
    auto substep = [&](const float* __restrict__ cur, const float* __restrict__ prv,
                       float* __restrict__ nxt,
                       u64 bn01, u64 bn23, u64 bs01, u64 bs23, float ampv) {
        u64 n01, n23;
        if (rg == 0) { n01 = bn01; n23 = bn23; }
        else {
            ulonglong2 v = *(const ulonglong2*)(cur + (lr0 - 1) * NXC + xcol);
            n01 = v.x; n23 = v.y;
        }
#pragma unroll
        for (int j = 0; j < RPT; j++) {
            const int lr = lr0 + j;
            const u64 cv01 = c01[j], cv23 = c23[j];
            const ulonglong2 pv = *(const ulonglong2*)(prv + lr * NXC + xcol);

            u64 s01, s23;
            if (j < RPT - 1) { s01 = c01[j + 1]; s23 = c23[j + 1]; }
            else if (rg == RG - 1) { s01 = bs01; s23 = bs23; }
            else {
                ulonglong2 v = *(const ulonglong2*)(cur + (lr + 1) * NXC + xcol);
                s01 = v.x; s23 = v.y;
            }

            const float lft = (xcol > 0)       ? cur[lr * NXC + xcol - 1] : 0.f;
            const float rgt = (xcol + 4 < NXC) ? cur[lr * NXC + xcol + 4] : 0.f;

            U2 nv = fdtd_pair(cv01, cv23, n01, n23, s01, s23, lft, rgt,
                              pv.x, pv.y, k01[j], k23[j]);

            if (shere && j == sj) {
                float2 lo = upk(nv.a), hi = upk(nv.b);
                if      (scomp == 0) lo.x += ampv;
                else if (scomp == 1) lo.y += ampv;
                else if (scomp == 2) hi.x += ampv;
                else                 hi.y += ampv;
                nv.a = pk(lo.x, lo.y);
                nv.b = pk(hi.x, hi.y);
            }

            ulonglong2 st; st.x = nv.a; st.y = nv.b;
            *(ulonglong2*)(nxt + lr * NXC + xcol) = st;

            c01[j] = nv.a; c23[j] = nv.b;
            n01 = cv01; n23 = cv23;
        }
    };

    // --- one double-step: (Pprev,Pcur) -> N1 (t+1) -> N2 (t+2), one sync -----
    auto dstep = [&](const float* Pprev, const float* Pcur,
                     float* N1, float* N2,
                     uint32_t poff, uint32_t coff, int t) {
        // prefetch ghost inputs (latency hidden behind substep 1)
        ulonglong2 G30 = {0,0}, G31 = {0,0}, GPn = {0,0};
        ulonglong2 S0v = {0,0}, S1v = {0,0}, GPs = {0,0};
        float GLn = 0.f, GRn = 0.f, GLs = 0.f, GRs = 0.f;
        if (bndN) {
            G30 = ld_dsmem_u64x2(nb30 + coff);
            G31 = ld_dsmem_u64x2(nb31 + coff);
            GPn = ld_dsmem_u64x2(nb31 + poff);
            if (xcol > 0)       GLn = ld_dsmem_f32(nb31 + coff - 4u);
            if (xcol + 4 < NXC) GRn = ld_dsmem_f32(nb31 + coff + 16u);
        }
        if (bndS) {
            S0v = ld_dsmem_u64x2(sb0 + coff);
            S1v = ld_dsmem_u64x2(sb1 + coff);
            GPs = ld_dsmem_u64x2(sb0 + poff);
            if (xcol > 0)       GLs = ld_dsmem_f32(sb0 + coff - 4u);
            if (xcol + 4 < NXC) GRs = ld_dsmem_f32(sb0 + coff + 16u);
        }

        // save time-t boundary rows (ghost compute needs them post-substep)
        const u64 old0a = c01[0],       old0b = c23[0];
        const u64 old1a = c01[RPT - 1], old1b = c23[RPT - 1];

        const float a1 = amp_s[t];

        // substep 1: t -> t+1 into N1
        substep(Pcur, Pprev, N1,
                bndN ? G31.x : 0, bndN ? G31.y : 0,
                bndS ? S0v.x : 0, bndS ? S0v.y : 0, a1);

        // ghost rows at t+1 (prefetched loads landed during substep 1)
        u64 gN01 = 0, gN23 = 0, gS01 = 0, gS23 = 0;
        if (bndN) {
            U2 g = fdtd_pair(G31.x, G31.y, G30.x, G30.y, old0a, old0b,
                             GLn, GRn, GPn.x, GPn.y, kg01, kg23);
            if (sghn) {
                float2 lo = upk(g.a), hi = upk(g.b);
                if      (scomp == 0) lo.x += a1;
                else if (scomp == 1) lo.y += a1;
                else if (scomp == 2) hi.x += a1;
                else                 hi.y += a1;
                g.a = pk(lo.x, lo.y); g.b = pk(hi.x, hi.y);
            }
            gN01 = g.a; gN23 = g.b;
        }
        if (bndS) {
            U2 g = fdtd_pair(S0v.x, S0v.y, old1a, old1b, S1v.x, S1v.y,
                             GLs, GRs, GPs.x, GPs.y, kg01, kg23);
            if (sghs) {
                float2 lo = upk(g.a), hi = upk(g.b);
                if      (scomp == 0) lo.x += a1;
                else if (scomp == 1) lo.y += a1;
                else if (scomp == 2) hi.x += a1;
                else                 hi.y += a1;
                g.a = pk(lo.x, lo.y); g.b = pk(hi.x, hi.y);
            }
            gS01 = g.a; gS23 = g.b;
        }

        __syncthreads();               // N1 visible CTA-wide
        if (samp) { *outp = N1[roff]; outp += NS * NREC; }

        // substep 2: t+1 -> t+2 into N2 (no cross-CTA data; ghosts in regs)
        substep(N1, Pcur, N2, gN01, gN23, gS01, gS23, amp_s[t + 1]);

        cluster_sync_();               // ONE cluster barrier per 2 steps
        if (samp) { *outp = N2[roff]; outp += NS * NREC; }
    };

    // --- main time loop: 4 steps per iteration, compile-time buffer rotation -
    for (int t4 = 0; t4 < NT; t4 += 4) {
        dstep(P0, P1, P2, P3, 0u,      1u * BB, t4);
        dstep(P2, P3, P0, P1, 2u * BB, 3u * BB, t4 + 2);
    }
}

// ---------------------------------------------------------------- launch
extern "C" void kernel_launch(void* const* d_in, const int* in_sizes, int n_in,
                              void* d_out, int out_size)
{
    const float* x   = (const float*)d_in[0];
    const float* vp  = (const float*)d_in[1];
    const int*   src = (const int*)d_in[2];
    const int*   rec = (const int*)d_in[3];
    float*       out = (float*)d_out;

    cudaFuncSetAttribute((const void*)wave_kernel,
                         cudaFuncAttributeMaxDynamicSharedMemorySize,
                         (int)SMEM_BYTES);

    wave_kernel<<<NS * CSZ, NTHREADS, SMEM_BYTES>>>(x, vp, src, rec, out);
}

// round 17
// speedup vs baseline: 2.2938x; 1.6893x over previous
#include <cuda_runtime.h>
#include <cstdint>

// 2D acoustic FDTD, 500 steps, 8 shots, 256x256, 128 recs/shot.
// One persistent kernel; shot = 8-CTA cluster; field in SMEM + registers.
// R14 body (packed-native f32x2, one barrier per step) with the barrier
// split into: syncthreads (STS drain) -> RELAXED cluster arrive (no L1
// flush / release fence; SMEM is physically coherent) -> receiver sample
// (overlaps barrier propagation) -> cluster wait.

#define DT 0.001f
#define DX 10.0f

constexpr int NT   = 500;
constexpr int NS   = 8;
constexpr int NZ   = 256;
constexpr int NXC  = 256;
constexpr int NREC = 128;

constexpr int CSZ  = 8;
constexpr int ROWS = NZ / CSZ;          // 32
constexpr int NTHREADS = 1024;
constexpr int COL4 = NXC / 4;           // 64
constexpr int RG   = NTHREADS / COL4;   // 16
constexpr int RPT  = ROWS / RG;         // 2

constexpr int BUF_ELEMS = ROWS * NXC;   // 8192
constexpr int OFF_AMP   = 2 * BUF_ELEMS;
constexpr size_t SMEM_BYTES = (size_t)(OFF_AMP + NT + 16) * sizeof(float);

typedef unsigned long long u64;

// ---------------------------------------------------------------- PTX helpers
__device__ __forceinline__ uint32_t cvta_smem(const void* p) {
    return (uint32_t)__cvta_generic_to_shared(p);
}
__device__ __forceinline__ uint32_t mapa_cluster(uint32_t laddr, uint32_t rank) {
    uint32_t r;
    asm("mapa.shared::cluster.u32 %0, %1, %2;" : "=r"(r) : "r"(laddr), "r"(rank));
    return r;
}
__device__ __forceinline__ ulonglong2 ld_dsmem_u64x2(uint32_t addr) {
    ulonglong2 v;
    asm volatile("ld.shared::cluster.v2.u64 {%0,%1}, [%2];"
                 : "=l"(v.x), "=l"(v.y) : "r"(addr));
    return v;
}
__device__ __forceinline__ void cluster_sync_() {
    asm volatile("barrier.cluster.arrive.aligned;" ::: "memory");
    asm volatile("barrier.cluster.wait.aligned;" ::: "memory");
}
__device__ __forceinline__ void cluster_arrive_relaxed_() {
    asm volatile("barrier.cluster.arrive.relaxed.aligned;" ::: "memory");
}
__device__ __forceinline__ void cluster_wait_() {
    asm volatile("barrier.cluster.wait.aligned;" ::: "memory");
}
__device__ __forceinline__ uint32_t cluster_rank_() {
    uint32_t r;
    asm("mov.u32 %0, %%cluster_ctarank;" : "=r"(r));
    return r;
}

// ---- packed f32x2 ops -------------------------------------------------------
__device__ __forceinline__ u64 pk(float a, float b) {
    u64 r; asm("mov.b64 %0, {%1, %2};" : "=l"(r) : "f"(a), "f"(b)); return r;
}
__device__ __forceinline__ float2 upk(u64 v) {
    float2 f; asm("mov.b64 {%0, %1}, %2;" : "=f"(f.x), "=f"(f.y) : "l"(v)); return f;
}
__device__ __forceinline__ u64 addx2(u64 a, u64 b) {
    u64 r; asm("add.rn.f32x2 %0, %1, %2;" : "=l"(r) : "l"(a), "l"(b)); return r;
}
__device__ __forceinline__ u64 mulx2(u64 a, u64 b) {
    u64 r; asm("mul.rn.f32x2 %0, %1, %2;" : "=l"(r) : "l"(a), "l"(b)); return r;
}
__device__ __forceinline__ u64 fmax2(u64 a, u64 b, u64 c) {
    u64 r; asm("fma.rn.f32x2 %0, %1, %2, %3;" : "=l"(r) : "l"(a), "l"(b), "l"(c)); return r;
}

// ---------------------------------------------------------------- kernel
__global__ void __cluster_dims__(CSZ, 1, 1) __launch_bounds__(NTHREADS, 1)
wave_kernel(const float* __restrict__ x,     // (NT, NS)
            const float* __restrict__ vp,    // (NZ, NXC)
            const int*   __restrict__ src,   // (NS, 2)
            const int*   __restrict__ rec,   // (NS, NREC, 2)
            float*       __restrict__ out)   // (NT, NS, NREC)
{
    extern __shared__ float sm[];
    float* buf0  = sm;
    float* buf1  = sm + BUF_ELEMS;
    float* amp_s = sm + OFF_AMP;

    __shared__ int rcnt;
    __shared__ int2 rlist[NREC];

    const int tid  = threadIdx.x;
    const uint32_t rank = cluster_rank_();
    const int shot = blockIdx.x / CSZ;

    const int col4 = tid & (COL4 - 1);
    const int rg   = tid >> 6;           // 0..15
    const int lr0  = rg * RPT;
    const int xcol = col4 * 4;
    const bool has_n = (rank > 0);
    const bool has_s = (rank < CSZ - 1);

    // --- init ----------------------------------------------------------------
    for (int i = tid; i < BUF_ELEMS; i += NTHREADS) { buf0[i] = 0.f; buf1[i] = 0.f; }
    for (int i = tid; i < NT; i += NTHREADS) {
        const int toff = (i + 2 < NT - 1) ? i + 2 : NT - 1;
        amp_s[i] = x[i * NS + shot] + x[toff * NS + shot];
    }
    if (tid == 0) rcnt = 0;
    __syncthreads();

    // claim receivers owned by this CTA
    if (tid < NREC) {
        const int gi = shot * NREC + tid;
        const int rz = rec[gi * 2 + 0];
        const int rx = rec[gi * 2 + 1];
        if ((uint32_t)(rz >> 5) == rank) {
            int s = atomicAdd(&rcnt, 1);
            rlist[s] = make_int2((rz & 31) * NXC + rx, shot * NREC + tid);
        }
    }

    // c2 in packed registers
    u64 k01[RPT], k23[RPT];
    const float sc = DT / DX;
#pragma unroll
    for (int j = 0; j < RPT; j++) {
        const int g = (int)rank * ROWS + lr0 + j;
        float4 v = *(const float4*)(vp + g * NXC + xcol);
        float a = v.x * sc, b = v.y * sc, c = v.z * sc, d = v.w * sc;
        k01[j] = pk(a * a, b * b);
        k23[j] = pk(c * c, d * d);
    }

    const u64 TWO2 = pk(2.f, 2.f);
    const u64 NEG4 = pk(-4.f, -4.f);
    const u64 NEG1 = pk(-1.f, -1.f);

    // packed-native field registers: cur pairs + negated prev pairs (zero @t=0)
    u64 c01[RPT], c23[RPT], np01[RPT], np23[RPT];
#pragma unroll
    for (int j = 0; j < RPT; j++) {
        c01[j] = 0; c23[j] = 0; np01[j] = 0; np23[j] = 0;
    }

    // source ownership
    const int sz = src[shot * 2 + 0];
    const int sx = src[shot * 2 + 1];
    const int sj = sz - ((int)rank * ROWS + lr0);
    const bool shere = (sj >= 0 && sj < RPT && sx >= xcol && sx < xcol + 4);
    const int scomp = sx - xcol;

    // DSMEM halo addresses (both parities)
    const uint32_t sa0 = cvta_smem(buf0);
    const uint32_t sa1 = cvta_smem(buf1);
    uint32_t nh0 = 0, nh1 = 0, sh0 = 0, sh1 = 0;
    if (rg == 0 && has_n) {
        const uint32_t off = (uint32_t)((ROWS - 1) * NXC + xcol) * 4u;
        nh0 = mapa_cluster(sa0 + off, rank - 1);
        nh1 = mapa_cluster(sa1 + off, rank - 1);
    }
    if (rg == RG - 1 && has_s) {
        const uint32_t off = (uint32_t)(xcol) * 4u;
        sh0 = mapa_cluster(sa0 + off, rank + 1);
        sh1 = mapa_cluster(sa1 + off, rank + 1);
    }

    __syncthreads();
    const bool samp = (tid < rcnt);
    int roff = 0;
    float* outp = out;
    if (samp) {
        int2 e = rlist[tid];
        roff = e.x;
        outp = out + e.y;
    }

    cluster_sync_();  // zeroed buffers visible cluster-wide

    // --- one FDTD step (packed-native; static register indices only) ---------
    auto step = [&](const float* __restrict__ cur, float* __restrict__ nxt,
                    uint32_t nh, uint32_t sh, int t) {
        // row above the strip (pairs)
        u64 n01, n23;
        if (rg == 0) {
            if (has_n) { ulonglong2 v = ld_dsmem_u64x2(nh); n01 = v.x; n23 = v.y; }
            else       { n01 = 0; n23 = 0; }
        } else {
            ulonglong2 v = *(const ulonglong2*)(cur + (lr0 - 1) * NXC + xcol);
            n01 = v.x; n23 = v.y;
        }

#pragma unroll
        for (int j = 0; j < RPT; j++) {
            const int lr = lr0 + j;
            const u64 cv01 = c01[j], cv23 = c23[j];

            u64 s01, s23;
            if (j < RPT - 1) {
                s01 = c01[j + 1]; s23 = c23[j + 1];
            } else if (rg == RG - 1) {
                if (has_s) { ulonglong2 v = ld_dsmem_u64x2(sh); s01 = v.x; s23 = v.y; }
                else       { s01 = 0; s23 = 0; }
            } else {
                ulonglong2 v = *(const ulonglong2*)(cur + (lr + 1) * NXC + xcol);
                s01 = v.x; s23 = v.y;
            }

            const float lft = (xcol > 0)       ? cur[lr * NXC + xcol - 1] : 0.f;
            const float rgt = (xcol + 4 < NXC) ? cur[lr * NXC + xcol + 4] : 0.f;

            const float2 clo = upk(cv01), chi = upk(cv23);
            const u64 L0 = pk(lft,   clo.x);
            const u64 M  = pk(clo.y, chi.x);
            const u64 R1 = pk(chi.y, rgt);

            u64 lap01 = addx2(addx2(n01, s01), addx2(L0, M));
            u64 lap23 = addx2(addx2(n23, s23), addx2(M, R1));
            lap01 = fmax2(cv01, NEG4, lap01);
            lap23 = fmax2(cv23, NEG4, lap23);

            u64 nv01 = fmax2(k01[j], lap01, fmax2(cv01, TWO2, np01[j]));
            u64 nv23 = fmax2(k23[j], lap23, fmax2(cv23, TWO2, np23[j]));

            np01[j] = mulx2(cv01, NEG1);
            np23[j] = mulx2(cv23, NEG1);

            // in-loop source injection; j is an unroll constant -> static regs
            if (shere && j == sj) {
                const float amp = amp_s[t];
                float2 lo = upk(nv01), hi = upk(nv23);
                if      (scomp == 0) lo.x += amp;
                else if (scomp == 1) lo.y += amp;
                else if (scomp == 2) hi.x += amp;
                else                 hi.y += amp;
                nv01 = pk(lo.x, lo.y);
                nv23 = pk(hi.x, hi.y);
            }

            ulonglong2 st; st.x = nv01; st.y = nv23;
            *(ulonglong2*)(nxt + lr * NXC + xcol) = st;

            c01[j] = nv01; c23[j] = nv23;
            n01 = cv01; n23 = cv23;
        }

        // ---- split relaxed cluster barrier ---------------------------------
        __syncthreads();             // BAR.SYNC drains STS: SMEM stores visible
        cluster_arrive_relaxed_();   // no release fence / L1 flush needed

        // overlap: receiver sampling (own SMEM, safe after syncthreads)
        if (samp) {
            *outp = nxt[roff];
            outp += NS * NREC;
        }

        cluster_wait_();             // all CTAs finished step t
    };

    // --- main time loop, unrolled x2 for compile-time buffer parity ----------
    for (int t2 = 0; t2 < NT; t2 += 2) {
        step(buf0, buf1, nh0, sh0, t2);
        step(buf1, buf0, nh1, sh1, t2 + 1);
    }
}

// ---------------------------------------------------------------- launch
extern "C" void kernel_launch(void* const* d_in, const int* in_sizes, int n_in,
                              void* d_out, int out_size)
{
    const float* x   = (const float*)d_in[0];
    const float* vp  = (const float*)d_in[1];
    const int*   src = (const int*)d_in[2];
    const int*   rec = (const int*)d_in[3];
    float*       out = (float*)d_out;

    cudaFuncSetAttribute((const void*)wave_kernel,
                         cudaFuncAttributeMaxDynamicSharedMemorySize,
                         (int)SMEM_BYTES);

    wave_kernel<<<NS * CSZ, NTHREADS, SMEM_BYTES>>>(x, vp, src, rec, out);
}